// round 2
// baseline (speedup 1.0000x reference)
#include <cuda_runtime.h>
#include <math.h>

// Problem dims
#define TB   2
#define TT   2048
#define TD   1024
#define TH   16
#define THD  64          // head dim
#define TDFF 4096
#define BT   (TB*TT)     // 4096 total rows

// ------------------------- scratch (device globals, no allocs) -------------
__device__ float g_h   [(size_t)BT * TD];        // LN output (reused for LN2)
__device__ float g_qkv [(size_t)BT * 3 * TD];    // [row][3072]: q | k | v
__device__ float g_o   [(size_t)BT * TD];        // attn output (concat heads)
__device__ float g_x2  [(size_t)BT * TD];        // x + attn
__device__ float g_ff  [(size_t)BT * TDFF];      // gelu(h2@W1+b1)
__device__ float g_wp  [(size_t)TD * 3 * TD];    // packed Wq|Wk|Wv -> [D][3D]

// ------------------------- weight pack: [H,D,K] -> [D][h*K+k] --------------
__global__ void pack_w_kernel(const float* __restrict__ Wq,
                              const float* __restrict__ Wk,
                              const float* __restrict__ Wv,
                              float* __restrict__ wp) {
    int idx = blockIdx.x * 256 + threadIdx.x;
    if (idx >= TD * 3 * TD) return;
    int d   = idx / (3 * TD);
    int col = idx - d * (3 * TD);
    const float* W = (col < TD) ? Wq : (col < 2 * TD ? Wk : Wv);
    int c = col & (TD - 1);
    int h = c >> 6;
    int k = c & 63;
    wp[idx] = W[((size_t)h * TD + d) * THD + k];
}

// ------------------------- LayerNorm: one block per row --------------------
__global__ void __launch_bounds__(256) ln_kernel(const float* __restrict__ x,
                                                 const float* __restrict__ g,
                                                 const float* __restrict__ b,
                                                 float* __restrict__ out) {
    __shared__ float sh[16];
    int row = blockIdx.x;
    int tid = threadIdx.x;
    const float* xr = x + (size_t)row * TD;
    float4 v = *(const float4*)(xr + tid * 4);
    float s  = v.x + v.y + v.z + v.w;
    float sq = v.x * v.x + v.y * v.y + v.z * v.z + v.w * v.w;
    #pragma unroll
    for (int o = 16; o; o >>= 1) {
        s  += __shfl_xor_sync(0xffffffffu, s, o);
        sq += __shfl_xor_sync(0xffffffffu, sq, o);
    }
    if ((tid & 31) == 0) { sh[tid >> 5] = s; sh[(tid >> 5) + 8] = sq; }
    __syncthreads();
    if (tid < 32) {
        float a = (tid < 8) ? sh[tid] : 0.0f;
        float c = (tid < 8) ? sh[tid + 8] : 0.0f;
        #pragma unroll
        for (int o = 4; o; o >>= 1) {
            a += __shfl_xor_sync(0xffffffffu, a, o);
            c += __shfl_xor_sync(0xffffffffu, c, o);
        }
        if (tid == 0) { sh[0] = a; sh[1] = c; }
    }
    __syncthreads();
    float mu  = sh[0] * (1.0f / TD);
    float var = sh[1] * (1.0f / TD) - mu * mu;
    float rs  = rsqrtf(var + 1e-5f);
    float4 gg = *(const float4*)(g + tid * 4);
    float4 bb = *(const float4*)(b + tid * 4);
    float4 o4;
    o4.x = (v.x - mu) * rs * gg.x + bb.x;
    o4.y = (v.y - mu) * rs * gg.y + bb.y;
    o4.z = (v.z - mu) * rs * gg.z + bb.z;
    o4.w = (v.w - mu) * rs * gg.w + bb.w;
    *(float4*)(out + (size_t)row * TD + tid * 4) = o4;
}

// ------------------------- generic SGEMM 128x128x8, 8x8 per thread ---------
// EPI bits: 1 = +bias[col], 2 = exact GELU, 4 = +res[row][col]
template <int EPI>
__global__ void __launch_bounds__(256) sgemm_kernel(
    const float* __restrict__ A, const float* __restrict__ B, float* __restrict__ C,
    int M, int N, int Kd, int lda, int ldb, int ldc,
    const float* __restrict__ bias, const float* __restrict__ res, int ldres) {
    __shared__ float As[8][128];
    __shared__ float Bs[8][128];
    int tid = threadIdx.x;
    int bm = blockIdx.y * 128, bn = blockIdx.x * 128;
    int arow = tid >> 1,  acol = (tid & 1) * 4;
    int brow = tid >> 5,  bcol = (tid & 31) * 4;
    int tx = tid & 15, ty = tid >> 4;
    const float* Ap = A + (size_t)(bm + arow) * lda + acol;
    const float* Bp = B + (size_t)brow * ldb + bn + bcol;
    float acc[8][8];
    #pragma unroll
    for (int i = 0; i < 8; i++)
        #pragma unroll
        for (int j = 0; j < 8; j++) acc[i][j] = 0.0f;

    for (int k0 = 0; k0 < Kd; k0 += 8) {
        float4 av = *(const float4*)(Ap + k0);
        float4 bv = *(const float4*)(Bp + (size_t)k0 * ldb);
        __syncthreads();
        As[acol + 0][arow] = av.x;
        As[acol + 1][arow] = av.y;
        As[acol + 2][arow] = av.z;
        As[acol + 3][arow] = av.w;
        *(float4*)&Bs[brow][bcol] = bv;
        __syncthreads();
        #pragma unroll
        for (int kk = 0; kk < 8; kk++) {
            float4 a0 = *(float4*)&As[kk][ty * 8];
            float4 a1 = *(float4*)&As[kk][ty * 8 + 4];
            float4 b0 = *(float4*)&Bs[kk][tx * 8];
            float4 b1 = *(float4*)&Bs[kk][tx * 8 + 4];
            float af[8] = {a0.x, a0.y, a0.z, a0.w, a1.x, a1.y, a1.z, a1.w};
            float bf[8] = {b0.x, b0.y, b0.z, b0.w, b1.x, b1.y, b1.z, b1.w};
            #pragma unroll
            for (int i = 0; i < 8; i++)
                #pragma unroll
                for (int j = 0; j < 8; j++) acc[i][j] = fmaf(af[i], bf[j], acc[i][j]);
        }
    }
    #pragma unroll
    for (int i = 0; i < 8; i++) {
        int r = bm + ty * 8 + i;
        #pragma unroll
        for (int j = 0; j < 8; j++) {
            int c = bn + tx * 8 + j;
            float v = acc[i][j];
            if (EPI & 1) v += bias[c];
            if (EPI & 2) v = 0.5f * v * (1.0f + erff(v * 0.70710678118654752f));
            if (EPI & 4) v += res[(size_t)r * ldres + c];
            C[(size_t)r * ldc + c] = v;
        }
    }
}

// ------------------------- fused causal flash attention --------------------
// One block per (query-tile ti, batch*head bh). 64x64 tiles, online softmax.
// Scores never touch HBM.
#define FA_SMEM (4 * 64 * 68 * 4)
__global__ void __launch_bounds__(256) flash_kernel(const float* __restrict__ qkv,
                                                    float* __restrict__ o) {
    extern __shared__ float sm[];
    float* Qs = sm;                 // [64][68]
    float* Ks = sm + 64 * 68;       // [64][68]
    float* Vs = sm + 2 * 64 * 68;   // [64][68]
    float* Ps = sm + 3 * 64 * 68;   // [64][68]

    int ti = blockIdx.x;
    int bh = blockIdx.y;
    int b = bh >> 4, h = bh & 15;
    int t0 = ti * 64;
    int tid = threadIdx.x;
    int tx = tid & 15, ty = tid >> 4;
    int i0 = ty * 4, j0 = tx * 4;

    const float* Qb = qkv + ((size_t)(b * TT + t0)) * (3 * TD) + h * THD;
    const float* Kb = qkv + ((size_t)b * TT) * (3 * TD) + TD + h * THD;
    const float* Vb = qkv + ((size_t)b * TT) * (3 * TD) + 2 * TD + h * THD;

    // load Q tile once
    #pragma unroll
    for (int l = 0; l < 4; l++) {
        int lin = tid + l * 256;
        int r = lin >> 4, c4 = (lin & 15) << 2;
        *(float4*)&Qs[r * 68 + c4] = *(const float4*)(Qb + (size_t)r * (3 * TD) + c4);
    }

    float m_prev[4], l_run[4], acc[4][4];
    #pragma unroll
    for (int i = 0; i < 4; i++) {
        m_prev[i] = -1e30f; l_run[i] = 0.0f;
        #pragma unroll
        for (int j = 0; j < 4; j++) acc[i][j] = 0.0f;
    }

    for (int sj = 0; sj <= ti; sj++) {
        int s0 = sj * 64;
        __syncthreads();
        #pragma unroll
        for (int l = 0; l < 4; l++) {
            int lin = tid + l * 256;
            int r = lin >> 4, c4 = (lin & 15) << 2;
            *(float4*)&Ks[r * 68 + c4] =
                *(const float4*)(Kb + (size_t)(s0 + r) * (3 * TD) + c4);
            *(float4*)&Vs[r * 68 + c4] =
                *(const float4*)(Vb + (size_t)(s0 + r) * (3 * TD) + c4);
        }
        __syncthreads();

        // S = Q K^T * scale
        float s[4][4] = {};
        #pragma unroll 8
        for (int k = 0; k < 64; k++) {
            float a[4], bb[4];
            #pragma unroll
            for (int i = 0; i < 4; i++) a[i]  = Qs[(i0 + i) * 68 + k];
            #pragma unroll
            for (int j = 0; j < 4; j++) bb[j] = Ks[(j0 + j) * 68 + k];
            #pragma unroll
            for (int i = 0; i < 4; i++)
                #pragma unroll
                for (int j = 0; j < 4; j++) s[i][j] = fmaf(a[i], bb[j], s[i][j]);
        }
        bool diag = (sj == ti);
        #pragma unroll
        for (int i = 0; i < 4; i++)
            #pragma unroll
            for (int j = 0; j < 4; j++) {
                float v = s[i][j] * 0.125f;
                if (diag && (s0 + j0 + j) > (t0 + i0 + i)) v = -1e30f;
                s[i][j] = v;
            }

        // online softmax update (row stats reduced across the 16 tx threads)
        #pragma unroll
        for (int i = 0; i < 4; i++) {
            float rmax = fmaxf(fmaxf(s[i][0], s[i][1]), fmaxf(s[i][2], s[i][3]));
            #pragma unroll
            for (int off = 8; off; off >>= 1)
                rmax = fmaxf(rmax, __shfl_xor_sync(0xffffffffu, rmax, off));
            float m_new = fmaxf(m_prev[i], rmax);
            float scale = expf(m_prev[i] - m_new);
            float rsum = 0.0f;
            #pragma unroll
            for (int j = 0; j < 4; j++) {
                float p = expf(s[i][j] - m_new);
                s[i][j] = p;
                rsum += p;
            }
            #pragma unroll
            for (int off = 8; off; off >>= 1)
                rsum += __shfl_xor_sync(0xffffffffu, rsum, off);
            l_run[i] = l_run[i] * scale + rsum;
            m_prev[i] = m_new;
            #pragma unroll
            for (int j = 0; j < 4; j++) acc[i][j] *= scale;
        }

        // stage P and accumulate O += P @ V
        #pragma unroll
        for (int i = 0; i < 4; i++)
            #pragma unroll
            for (int j = 0; j < 4; j++) Ps[(i0 + i) * 68 + j0 + j] = s[i][j];
        __syncthreads();
        #pragma unroll 8
        for (int ss = 0; ss < 64; ss++) {
            float pv[4], vv[4];
            #pragma unroll
            for (int i = 0; i < 4; i++) pv[i] = Ps[(i0 + i) * 68 + ss];
            #pragma unroll
            for (int j = 0; j < 4; j++) vv[j] = Vs[ss * 68 + j0 + j];
            #pragma unroll
            for (int i = 0; i < 4; i++)
                #pragma unroll
                for (int j = 0; j < 4; j++) acc[i][j] = fmaf(pv[i], vv[j], acc[i][j]);
        }
    }

    #pragma unroll
    for (int i = 0; i < 4; i++) {
        float inv = 1.0f / l_run[i];
        #pragma unroll
        for (int j = 0; j < 4; j++)
            o[((size_t)(b * TT + t0 + i0 + i)) * TD + h * THD + j0 + j] =
                acc[i][j] * inv;
    }
}

// ------------------------- launch ------------------------------------------
extern "C" void kernel_launch(void* const* d_in, const int* in_sizes, int n_in,
                              void* d_out, int out_size) {
    const float* x   = (const float*)d_in[0];
    const float* Wq  = (const float*)d_in[1];
    const float* Wk  = (const float*)d_in[2];
    const float* Wv  = (const float*)d_in[3];
    const float* Wo  = (const float*)d_in[4];
    const float* bo  = (const float*)d_in[5];
    const float* W1  = (const float*)d_in[6];
    const float* b1  = (const float*)d_in[7];
    const float* W2  = (const float*)d_in[8];
    const float* b2  = (const float*)d_in[9];
    const float* g1  = (const float*)d_in[10];
    const float* be1 = (const float*)d_in[11];
    const float* g2  = (const float*)d_in[12];
    const float* be2 = (const float*)d_in[13];
    float* out = (float*)d_out;

    float *h, *qkv, *o, *x2, *ff, *wp;
    cudaGetSymbolAddress((void**)&h,   g_h);
    cudaGetSymbolAddress((void**)&qkv, g_qkv);
    cudaGetSymbolAddress((void**)&o,   g_o);
    cudaGetSymbolAddress((void**)&x2,  g_x2);
    cudaGetSymbolAddress((void**)&ff,  g_ff);
    cudaGetSymbolAddress((void**)&wp,  g_wp);

    static int smem_set = 0;
    if (!smem_set) {
        cudaFuncSetAttribute(flash_kernel,
                             cudaFuncAttributeMaxDynamicSharedMemorySize, FA_SMEM);
        smem_set = 1;
    }

    // 1. pack per-head qkv weights into one [D][3D] matrix
    pack_w_kernel<<<(TD * 3 * TD + 255) / 256, 256>>>(Wq, Wk, Wv, wp);
    // 2. LN1
    ln_kernel<<<BT, 256>>>(x, g1, be1, h);
    // 3. fused QKV gemm: [4096,1024] @ [1024,3072]
    sgemm_kernel<0><<<dim3(24, 32), 256>>>(h, wp, qkv, BT, 3 * TD, TD,
                                           TD, 3 * TD, 3 * TD, nullptr, nullptr, 0);
    // 4-6. fused causal attention (scores stay in SMEM)
    flash_kernel<<<dim3(32, TB * TH), 256, FA_SMEM>>>(qkv, o);
    // 7. x2 = x + o @ Wo + bo
    sgemm_kernel<5><<<dim3(8, 32), 256>>>(o, Wo, x2, BT, TD, TD,
                                          TD, TD, TD, bo, x, TD);
    // 8. LN2
    ln_kernel<<<BT, 256>>>(x2, g2, be2, h);
    // 9. ff = gelu(h @ W1 + b1)
    sgemm_kernel<3><<<dim3(32, 32), 256>>>(h, W1, ff, BT, TDFF, TD,
                                           TD, TDFF, TDFF, b1, nullptr, 0);
    // 10. out = x2 + ff @ W2 + b2
    sgemm_kernel<5><<<dim3(8, 32), 256>>>(ff, W2, out, BT, TD, TDFF,
                                          TDFF, TD, TD, b2, x2, TD);
}

// round 5
// speedup vs baseline: 1.1252x; 1.1252x over previous
#include <cuda_runtime.h>
#include <math.h>

// Problem dims
#define TB   2
#define TT   2048
#define TD   1024
#define TH   16
#define THD  64          // head dim
#define TDFF 4096
#define BT   (TB*TT)     // 4096 total rows

// ------------------------- scratch (device globals, no allocs) -------------
__device__ float g_h   [(size_t)BT * TD];        // LN output (reused for LN2)
__device__ float g_qkv [(size_t)BT * 3 * TD];    // [row][3072]: q | k | v
__device__ float g_o   [(size_t)BT * TD];        // attn output (concat heads)
__device__ float g_x2  [(size_t)BT * TD];        // x + attn
__device__ float g_ff  [(size_t)BT * TDFF];      // gelu(h2@W1+b1)
__device__ float g_wp  [(size_t)TD * 3 * TD];    // packed Wq|Wk|Wv -> [D][3D]

// ------------------------- weight pack: [H,D,K] -> [D][h*K+k] --------------
__global__ void pack_w_kernel(const float* __restrict__ Wq,
                              const float* __restrict__ Wk,
                              const float* __restrict__ Wv,
                              float* __restrict__ wp) {
    int idx = blockIdx.x * 256 + threadIdx.x;
    if (idx >= TD * 3 * TD) return;
    int d   = idx / (3 * TD);
    int col = idx - d * (3 * TD);
    const float* W = (col < TD) ? Wq : (col < 2 * TD ? Wk : Wv);
    int c = col & (TD - 1);
    int h = c >> 6;
    int k = c & 63;
    wp[idx] = W[((size_t)h * TD + d) * THD + k];
}

// ------------------------- LayerNorm: one block per row --------------------
__global__ void __launch_bounds__(256) ln_kernel(const float* __restrict__ x,
                                                 const float* __restrict__ g,
                                                 const float* __restrict__ b,
                                                 float* __restrict__ out) {
    __shared__ float sh[16];
    int row = blockIdx.x;
    int tid = threadIdx.x;
    const float* xr = x + (size_t)row * TD;
    float4 v = *(const float4*)(xr + tid * 4);
    float s  = v.x + v.y + v.z + v.w;
    float sq = v.x * v.x + v.y * v.y + v.z * v.z + v.w * v.w;
    #pragma unroll
    for (int o = 16; o; o >>= 1) {
        s  += __shfl_xor_sync(0xffffffffu, s, o);
        sq += __shfl_xor_sync(0xffffffffu, sq, o);
    }
    if ((tid & 31) == 0) { sh[tid >> 5] = s; sh[(tid >> 5) + 8] = sq; }
    __syncthreads();
    if (tid < 32) {
        float a = (tid < 8) ? sh[tid] : 0.0f;
        float c = (tid < 8) ? sh[tid + 8] : 0.0f;
        #pragma unroll
        for (int o = 4; o; o >>= 1) {
            a += __shfl_xor_sync(0xffffffffu, a, o);
            c += __shfl_xor_sync(0xffffffffu, c, o);
        }
        if (tid == 0) { sh[0] = a; sh[1] = c; }
    }
    __syncthreads();
    float mu  = sh[0] * (1.0f / TD);
    float var = sh[1] * (1.0f / TD) - mu * mu;
    float rs  = rsqrtf(var + 1e-5f);
    float4 gg = *(const float4*)(g + tid * 4);
    float4 bb = *(const float4*)(b + tid * 4);
    float4 o4;
    o4.x = (v.x - mu) * rs * gg.x + bb.x;
    o4.y = (v.y - mu) * rs * gg.y + bb.y;
    o4.z = (v.z - mu) * rs * gg.z + bb.z;
    o4.w = (v.w - mu) * rs * gg.w + bb.w;
    *(float4*)(out + (size_t)row * TD + tid * 4) = o4;
}

// ------------------------- SGEMM v2: 128x128x16, reg-prefetch --------------
// EPI bits: 1 = +bias[col], 2 = exact GELU, 4 = +res[row][col]
template <int EPI>
__global__ void __launch_bounds__(256) sgemm_kernel(
    const float* __restrict__ A, const float* __restrict__ B, float* __restrict__ C,
    int M, int N, int Kd, int lda, int ldb, int ldc,
    const float* __restrict__ bias, const float* __restrict__ res, int ldres) {
    __shared__ float As[16][132];   // k-major, padded (conflict-free transp. store)
    __shared__ float Bs[16][128];
    int tid = threadIdx.x;
    int bm = blockIdx.y * 128, bn = blockIdx.x * 128;
    int tx = tid & 15, ty = tid >> 4;
    int arow = tid >> 1, acol = (tid & 1) * 4;  // A: 128 rows x 16 k, 2 float4/thr
    int brow = tid >> 5, bcol = (tid & 31) * 4; // B: 16 k x 128 n, 2 float4/thr
    const float* Ap = A + (size_t)(bm + arow) * lda + acol;
    const float* Bp = B + (size_t)brow * ldb + bn + bcol;

    float acc[8][8];
    #pragma unroll
    for (int i = 0; i < 8; i++)
        #pragma unroll
        for (int j = 0; j < 8; j++) acc[i][j] = 0.0f;

    // prefetch k0 = 0
    float4 pa0 = *(const float4*)(Ap);
    float4 pa1 = *(const float4*)(Ap + 8);
    float4 pb0 = *(const float4*)(Bp);
    float4 pb1 = *(const float4*)(Bp + (size_t)8 * ldb);

    for (int k0 = 0; k0 < Kd; k0 += 16) {
        if (k0) __syncthreads();
        // store prefetched tile (A transposed, conflict-free)
        As[acol + 0][arow] = pa0.x;
        As[acol + 1][arow] = pa0.y;
        As[acol + 2][arow] = pa0.z;
        As[acol + 3][arow] = pa0.w;
        As[acol + 8][arow] = pa1.x;
        As[acol + 9][arow] = pa1.y;
        As[acol + 10][arow] = pa1.z;
        As[acol + 11][arow] = pa1.w;
        *(float4*)&Bs[brow][bcol] = pb0;
        *(float4*)&Bs[brow + 8][bcol] = pb1;
        __syncthreads();
        // issue next gmem loads early — overlap with compute below
        if (k0 + 16 < Kd) {
            pa0 = *(const float4*)(Ap + k0 + 16);
            pa1 = *(const float4*)(Ap + k0 + 24);
            pb0 = *(const float4*)(Bp + (size_t)(k0 + 16) * ldb);
            pb1 = *(const float4*)(Bp + (size_t)(k0 + 24) * ldb);
        }
        #pragma unroll
        for (int kk = 0; kk < 16; kk++) {
            float4 a0 = *(float4*)&As[kk][ty * 8];
            float4 a1 = *(float4*)&As[kk][ty * 8 + 4];
            float4 b0 = *(float4*)&Bs[kk][tx * 8];
            float4 b1 = *(float4*)&Bs[kk][tx * 8 + 4];
            float af[8] = {a0.x, a0.y, a0.z, a0.w, a1.x, a1.y, a1.z, a1.w};
            float bf[8] = {b0.x, b0.y, b0.z, b0.w, b1.x, b1.y, b1.z, b1.w};
            #pragma unroll
            for (int i = 0; i < 8; i++)
                #pragma unroll
                for (int j = 0; j < 8; j++) acc[i][j] = fmaf(af[i], bf[j], acc[i][j]);
        }
    }
    #pragma unroll
    for (int i = 0; i < 8; i++) {
        int r = bm + ty * 8 + i;
        #pragma unroll
        for (int j = 0; j < 8; j++) {
            int c = bn + tx * 8 + j;
            float v = acc[i][j];
            if (EPI & 1) v += bias[c];
            if (EPI & 2) v = 0.5f * v * (1.0f + erff(v * 0.70710678118654752f));
            if (EPI & 4) v += res[(size_t)r * ldres + c];
            C[(size_t)r * ldc + c] = v;
        }
    }
}

// ------------------------- fused causal flash attention v2 -----------------
// Q/K stored k-major (transposed) in SMEM -> float4 LDS in the MMA loops.
#define FA_SMEM (4 * 64 * 68 * 4)
__global__ void __launch_bounds__(256) flash_kernel(const float* __restrict__ qkv,
                                                    float* __restrict__ o) {
    extern __shared__ float sm[];
    float* Qt = sm;                 // [k=64][row 64] pad 68
    float* Kt = sm + 64 * 68;       // [k=64][col 64] pad 68
    float* Vs = sm + 2 * 64 * 68;   // [s=64][d 64]   pad 68 (row-major)
    float* Ps = sm + 3 * 64 * 68;   // [t=64][s 64]   pad 68 (row-major)

    int ti = blockIdx.x;
    int bh = blockIdx.y;
    int b = bh >> 4, h = bh & 15;
    int t0 = ti * 64;
    int tid = threadIdx.x;
    int tx = tid & 15, ty = tid >> 4;
    int i0 = ty * 4, j0 = tx * 4;

    const float* Qb = qkv + ((size_t)(b * TT + t0)) * (3 * TD) + h * THD;
    const float* Kb = qkv + ((size_t)b * TT) * (3 * TD) + TD + h * THD;
    const float* Vb = qkv + ((size_t)b * TT) * (3 * TD) + 2 * TD + h * THD;

    // load Q tile transposed (conflict-free scalar stores; 16B gmem reads)
    #pragma unroll
    for (int l = 0; l < 4; l++) {
        int lin = tid + l * 256;
        int r = lin & 63, k4 = (lin >> 6) << 2;
        float4 q = *(const float4*)(Qb + (size_t)r * (3 * TD) + k4);
        Qt[(k4 + 0) * 68 + r] = q.x;
        Qt[(k4 + 1) * 68 + r] = q.y;
        Qt[(k4 + 2) * 68 + r] = q.z;
        Qt[(k4 + 3) * 68 + r] = q.w;
    }

    float m_prev[4], l_run[4], acc[4][4];
    #pragma unroll
    for (int i = 0; i < 4; i++) {
        m_prev[i] = -1e30f; l_run[i] = 0.0f;
        #pragma unroll
        for (int j = 0; j < 4; j++) acc[i][j] = 0.0f;
    }

    for (int sj = 0; sj <= ti; sj++) {
        int s0 = sj * 64;
        __syncthreads();
        #pragma unroll
        for (int l = 0; l < 4; l++) {
            int lin = tid + l * 256;
            // K transposed
            int r = lin & 63, k4 = (lin >> 6) << 2;
            float4 kv = *(const float4*)(Kb + (size_t)(s0 + r) * (3 * TD) + k4);
            Kt[(k4 + 0) * 68 + r] = kv.x;
            Kt[(k4 + 1) * 68 + r] = kv.y;
            Kt[(k4 + 2) * 68 + r] = kv.z;
            Kt[(k4 + 3) * 68 + r] = kv.w;
            // V row-major (coalesced)
            int rv = lin >> 4, c4 = (lin & 15) << 2;
            *(float4*)&Vs[rv * 68 + c4] =
                *(const float4*)(Vb + (size_t)(s0 + rv) * (3 * TD) + c4);
        }
        __syncthreads();

        // S = Q K^T * scale : outer product over k, 2x LDS.128 per k
        float s[4][4] = {};
        #pragma unroll 4
        for (int k = 0; k < 64; k++) {
            float4 qa = *(float4*)&Qt[k * 68 + i0];
            float4 kb = *(float4*)&Kt[k * 68 + j0];
            float af[4] = {qa.x, qa.y, qa.z, qa.w};
            float bf[4] = {kb.x, kb.y, kb.z, kb.w};
            #pragma unroll
            for (int i = 0; i < 4; i++)
                #pragma unroll
                for (int j = 0; j < 4; j++) s[i][j] = fmaf(af[i], bf[j], s[i][j]);
        }
        bool diag = (sj == ti);
        #pragma unroll
        for (int i = 0; i < 4; i++)
            #pragma unroll
            for (int j = 0; j < 4; j++) {
                float v = s[i][j] * 0.125f;
                if (diag && (s0 + j0 + j) > (t0 + i0 + i)) v = -1e30f;
                s[i][j] = v;
            }

        // online softmax (row stats across the 16 tx threads)
        #pragma unroll
        for (int i = 0; i < 4; i++) {
            float rmax = fmaxf(fmaxf(s[i][0], s[i][1]), fmaxf(s[i][2], s[i][3]));
            #pragma unroll
            for (int off = 8; off; off >>= 1)
                rmax = fmaxf(rmax, __shfl_xor_sync(0xffffffffu, rmax, off));
            float m_new = fmaxf(m_prev[i], rmax);
            float scale = __expf(m_prev[i] - m_new);
            float rsum = 0.0f;
            #pragma unroll
            for (int j = 0; j < 4; j++) {
                float p = __expf(s[i][j] - m_new);
                s[i][j] = p;
                rsum += p;
            }
            #pragma unroll
            for (int off = 8; off; off >>= 1)
                rsum += __shfl_xor_sync(0xffffffffu, rsum, off);
            l_run[i] = l_run[i] * scale + rsum;
            m_prev[i] = m_new;
            #pragma unroll
            for (int j = 0; j < 4; j++) acc[i][j] *= scale;
        }

        // stage P (row-major) and accumulate O += P @ V
        #pragma unroll
        for (int i = 0; i < 4; i++)
            #pragma unroll
            for (int j = 0; j < 4; j++) Ps[(i0 + i) * 68 + j0 + j] = s[i][j];
        __syncthreads();
        #pragma unroll 4
        for (int ss = 0; ss < 64; ss++) {
            float4 vv = *(float4*)&Vs[ss * 68 + j0];
            float pv[4];
            #pragma unroll
            for (int i = 0; i < 4; i++) pv[i] = Ps[(i0 + i) * 68 + ss];
            float vf[4] = {vv.x, vv.y, vv.z, vv.w};
            #pragma unroll
            for (int i = 0; i < 4; i++)
                #pragma unroll
                for (int j = 0; j < 4; j++) acc[i][j] = fmaf(pv[i], vf[j], acc[i][j]);
        }
    }

    #pragma unroll
    for (int i = 0; i < 4; i++) {
        float inv = 1.0f / l_run[i];
        #pragma unroll
        for (int j = 0; j < 4; j++)
            o[((size_t)(b * TT + t0 + i0 + i)) * TD + h * THD + j0 + j] =
                acc[i][j] * inv;
    }
}

// ------------------------- launch ------------------------------------------
extern "C" void kernel_launch(void* const* d_in, const int* in_sizes, int n_in,
                              void* d_out, int out_size) {
    const float* x   = (const float*)d_in[0];
    const float* Wq  = (const float*)d_in[1];
    const float* Wk  = (const float*)d_in[2];
    const float* Wv  = (const float*)d_in[3];
    const float* Wo  = (const float*)d_in[4];
    const float* bo  = (const float*)d_in[5];
    const float* W1  = (const float*)d_in[6];
    const float* b1  = (const float*)d_in[7];
    const float* W2  = (const float*)d_in[8];
    const float* b2  = (const float*)d_in[9];
    const float* g1  = (const float*)d_in[10];
    const float* be1 = (const float*)d_in[11];
    const float* g2  = (const float*)d_in[12];
    const float* be2 = (const float*)d_in[13];
    float* out = (float*)d_out;

    float *h, *qkv, *o, *x2, *ff, *wp;
    cudaGetSymbolAddress((void**)&h,   g_h);
    cudaGetSymbolAddress((void**)&qkv, g_qkv);
    cudaGetSymbolAddress((void**)&o,   g_o);
    cudaGetSymbolAddress((void**)&x2,  g_x2);
    cudaGetSymbolAddress((void**)&ff,  g_ff);
    cudaGetSymbolAddress((void**)&wp,  g_wp);

    static int smem_set = 0;
    if (!smem_set) {
        cudaFuncSetAttribute(flash_kernel,
                             cudaFuncAttributeMaxDynamicSharedMemorySize, FA_SMEM);
        smem_set = 1;
    }

    // 1. pack per-head qkv weights into one [D][3D] matrix
    pack_w_kernel<<<(TD * 3 * TD + 255) / 256, 256>>>(Wq, Wk, Wv, wp);
    // 2. LN1
    ln_kernel<<<BT, 256>>>(x, g1, be1, h);
    // 3. fused QKV gemm: [4096,1024] @ [1024,3072]
    sgemm_kernel<0><<<dim3(24, 32), 256>>>(h, wp, qkv, BT, 3 * TD, TD,
                                           TD, 3 * TD, 3 * TD, nullptr, nullptr, 0);
    // 4-6. fused causal attention (scores stay in SMEM)
    flash_kernel<<<dim3(32, TB * TH), 256, FA_SMEM>>>(qkv, o);
    // 7. x2 = x + o @ Wo + bo
    sgemm_kernel<5><<<dim3(8, 32), 256>>>(o, Wo, x2, BT, TD, TD,
                                          TD, TD, TD, bo, x, TD);
    // 8. LN2
    ln_kernel<<<BT, 256>>>(x2, g2, be2, h);
    // 9. ff = gelu(h @ W1 + b1)
    sgemm_kernel<3><<<dim3(32, 32), 256>>>(h, W1, ff, BT, TDFF, TD,
                                           TD, TDFF, TDFF, b1, nullptr, 0);
    // 10. out = x2 + ff @ W2 + b2
    sgemm_kernel<5><<<dim3(8, 32), 256>>>(ff, W2, out, BT, TD, TDFF,
                                          TDFF, TD, TD, b2, x2, TD);
}

// round 7
// speedup vs baseline: 1.9996x; 1.7772x over previous
#include <cuda_runtime.h>
#include <cuda_bf16.h>
#include <math.h>
#include <stdint.h>

// Problem dims
#define TB   2
#define TT   2048
#define TD   1024
#define TH   16
#define THD  64
#define TDFF 4096
#define BT   (TB*TT)

// ------------------------- scratch (device globals) ------------------------
// A-operands stored physically as (hi | lo), each block K wide: [M][2K]
__device__ __nv_bfloat16 g_hA  [(size_t)BT * 2 * TD];
__device__ float         g_qkv [(size_t)BT * 3 * TD];
__device__ __nv_bfloat16 g_oA  [(size_t)BT * 2 * TD];
__device__ float         g_x2  [(size_t)BT * TD];
__device__ __nv_bfloat16 g_ffA [(size_t)BT * 2 * TDFF];
// B-operands (weights), K-major [N][2K]: (hi | lo)
__device__ __nv_bfloat16 g_wqkv[(size_t)(3*TD) * (2*TD)];
__device__ __nv_bfloat16 g_wo  [(size_t)TD * (2*TD)];
__device__ __nv_bfloat16 g_w1  [(size_t)TDFF * (2*TD)];
__device__ __nv_bfloat16 g_w2  [(size_t)TD * (2*TDFF)];

__device__ __forceinline__ uint32_t smem_u32(const void* p) {
    uint32_t a;
    asm("{ .reg .u64 t; cvta.to.shared.u64 t, %1; cvt.u32.u64 %0, t; }"
        : "=r"(a) : "l"(p));
    return a;
}
__device__ __forceinline__ void bf16split(float v, __nv_bfloat16& hi,
                                          __nv_bfloat16& lo) {
    hi = __float2bfloat16(v);
    lo = __float2bfloat16(v - __bfloat162float(hi));
}
__device__ __forceinline__ void cp16(uint32_t sdst, const void* gsrc) {
    asm volatile("cp.async.cg.shared.global [%0], [%1], 16;"
                 :: "r"(sdst), "l"(gsrc));
}
__device__ __forceinline__ void ldm4(uint32_t addr, uint32_t& r0, uint32_t& r1,
                                     uint32_t& r2, uint32_t& r3) {
    asm volatile("ldmatrix.sync.aligned.m8n8.x4.shared.b16 {%0,%1,%2,%3}, [%4];"
                 : "=r"(r0), "=r"(r1), "=r"(r2), "=r"(r3) : "r"(addr));
}
__device__ __forceinline__ void mma16816(float* d, const uint32_t* a,
                                         uint32_t b0, uint32_t b1) {
    asm volatile(
        "mma.sync.aligned.m16n8k16.row.col.f32.bf16.bf16.f32 "
        "{%0,%1,%2,%3}, {%4,%5,%6,%7}, {%8,%9}, {%0,%1,%2,%3};"
        : "+f"(d[0]), "+f"(d[1]), "+f"(d[2]), "+f"(d[3])
        : "r"(a[0]), "r"(a[1]), "r"(a[2]), "r"(a[3]), "r"(b0), "r"(b1));
}

// ------------------------- weight convert (tiled transpose + split) --------
__global__ void __launch_bounds__(256) wconv_kernel(
    const float* __restrict__ src, int srcld,
    __nv_bfloat16* __restrict__ dst, int dstld, int khalf) {
    __shared__ float t[32][33];
    int k0 = blockIdx.y * 32, n0 = blockIdx.x * 32;
    int tx = threadIdx.x, ty = threadIdx.y;
    #pragma unroll
    for (int i = 0; i < 4; i++)
        t[ty + 8 * i][tx] = src[(size_t)(k0 + ty + 8 * i) * srcld + n0 + tx];
    __syncthreads();
    #pragma unroll
    for (int i = 0; i < 4; i++) {
        int n = n0 + ty + 8 * i, k = k0 + tx;
        __nv_bfloat16 hi, lo;
        bf16split(t[tx][ty + 8 * i], hi, lo);
        dst[(size_t)n * dstld + k] = hi;
        dst[(size_t)n * dstld + khalf + k] = lo;
    }
}

__global__ void __launch_bounds__(256) qkvconv_kernel(
    const float* __restrict__ Wq, const float* __restrict__ Wk,
    const float* __restrict__ Wv, __nv_bfloat16* __restrict__ dst) {
    __shared__ float t[32][33];
    int z = blockIdx.z;
    int third = z >> 4, h = z & 15;
    const float* W = (third == 0) ? Wq : ((third == 1) ? Wk : Wv);
    const float* src = W + (size_t)h * TD * THD;   // [1024][64]
    int k0 = blockIdx.y * 32, n0 = blockIdx.x * 32;
    int tx = threadIdx.x, ty = threadIdx.y;
    #pragma unroll
    for (int i = 0; i < 4; i++)
        t[ty + 8 * i][tx] = src[(size_t)(k0 + ty + 8 * i) * THD + n0 + tx];
    __syncthreads();
    #pragma unroll
    for (int i = 0; i < 4; i++) {
        int nl = n0 + ty + 8 * i, k = k0 + tx;
        int n = third * TD + h * THD + nl;
        __nv_bfloat16 hi, lo;
        bf16split(t[tx][ty + 8 * i], hi, lo);
        dst[(size_t)n * (2 * TD) + k] = hi;
        dst[(size_t)n * (2 * TD) + TD + k] = lo;
    }
}

// ------------------------- LayerNorm -> split bf16 A operand ---------------
__global__ void __launch_bounds__(256) ln_kernel(const float* __restrict__ x,
                                                 const float* __restrict__ g,
                                                 const float* __restrict__ b,
                                                 __nv_bfloat16* __restrict__ outA) {
    __shared__ float sh[16];
    int row = blockIdx.x;
    int tid = threadIdx.x;
    const float* xr = x + (size_t)row * TD;
    float4 v = *(const float4*)(xr + tid * 4);
    float s  = v.x + v.y + v.z + v.w;
    float sq = v.x * v.x + v.y * v.y + v.z * v.z + v.w * v.w;
    #pragma unroll
    for (int o = 16; o; o >>= 1) {
        s  += __shfl_xor_sync(0xffffffffu, s, o);
        sq += __shfl_xor_sync(0xffffffffu, sq, o);
    }
    if ((tid & 31) == 0) { sh[tid >> 5] = s; sh[(tid >> 5) + 8] = sq; }
    __syncthreads();
    if (tid < 32) {
        float a = (tid < 8) ? sh[tid] : 0.0f;
        float c = (tid < 8) ? sh[tid + 8] : 0.0f;
        #pragma unroll
        for (int o = 4; o; o >>= 1) {
            a += __shfl_xor_sync(0xffffffffu, a, o);
            c += __shfl_xor_sync(0xffffffffu, c, o);
        }
        if (tid == 0) { sh[0] = a; sh[1] = c; }
    }
    __syncthreads();
    float mu  = sh[0] * (1.0f / TD);
    float var = sh[1] * (1.0f / TD) - mu * mu;
    float rs  = rsqrtf(var + 1e-5f);
    float4 gg = *(const float4*)(g + tid * 4);
    float4 bb = *(const float4*)(b + tid * 4);
    float o0 = (v.x - mu) * rs * gg.x + bb.x;
    float o1 = (v.y - mu) * rs * gg.y + bb.y;
    float o2 = (v.z - mu) * rs * gg.z + bb.z;
    float o3 = (v.w - mu) * rs * gg.w + bb.w;
    __nv_bfloat16 h0, l0, h1, l1, h2, l2, h3, l3;
    bf16split(o0, h0, l0); bf16split(o1, h1, l1);
    bf16split(o2, h2, l2); bf16split(o3, h3, l3);
    __nv_bfloat16* base = outA + (size_t)row * (2 * TD) + tid * 4;
    *(__nv_bfloat162*)(base + 0) = __halves2bfloat162(h0, h1);
    *(__nv_bfloat162*)(base + 2) = __halves2bfloat162(h2, h3);
    *(__nv_bfloat162*)(base + TD + 0) = __halves2bfloat162(l0, l1);
    *(__nv_bfloat162*)(base + TD + 2) = __halves2bfloat162(l2, l3);
}

// ------------------------- HMMA split-bf16 GEMM ----------------------------
// C[M,N] = A @ B^T over logical K''=3K: A blocks (hi,lo,hi), B (hi,hi,lo).
// 128x128 CTA tile, 8 warps x (32x64), m16n8k16, cp.async double buffer.
// EPI: 0 fp32 store; 1 +bias+res fp32; 2 +bias, GELU, bf16 hi/lo split store
#define MSTRIDE 72                      // bf16 elements per smem row
#define STG     (128 * MSTRIDE * 2)     // bytes per operand stage = 18432
#define MDYN    (4 * STG)               // 73728

template <int EPI>
__global__ void __launch_bounds__(256) mgemm_kernel(
    const __nv_bfloat16* __restrict__ A, const __nv_bfloat16* __restrict__ B,
    float* __restrict__ Cf, __nv_bfloat16* __restrict__ Cb,
    int K, int ldA, int ldB, int ldc, int khalf,
    const float* __restrict__ bias, const float* __restrict__ res, int ldres) {
    extern __shared__ char smp[];
    uint32_t smb = smem_u32(smp);
    int tid = threadIdx.x, wid = tid >> 5, lane = tid & 31;
    int bm = blockIdx.y * 128, bn = blockIdx.x * 128;
    int wm = (wid & 3) * 32, wn = (wid >> 2) * 64;
    const int S = (3 * K) >> 6;         // stages of 64 logical k

    int arow = tid >> 3, acol = (tid & 7) * 8;   // 32 rows/pass, 4 passes

    float acc[2][8][4];
    #pragma unroll
    for (int i = 0; i < 2; i++)
        #pragma unroll
        for (int j = 0; j < 8; j++)
            #pragma unroll
            for (int q = 0; q < 4; q++) acc[i][j][q] = 0.0f;

    // ---- stage issue: cp.async 64-wide k slab of A and B ----
    auto issue = [&](int s) {
        int k0 = s << 6;
        int blk = k0 / K, cin = k0 - blk * K;
        int acb = ((blk == 1) ? K : 0) + cin;
        int bcb = ((blk == 2) ? K : 0) + cin;
        uint32_t sa = smb + (s & 1) * STG;
        uint32_t sb = smb + 2 * STG + (s & 1) * STG;
        #pragma unroll
        for (int p = 0; p < 4; p++) {
            int r = p * 32 + arow;
            cp16(sa + r * (MSTRIDE * 2) + acol * 2,
                 A + (size_t)(bm + r) * ldA + acb + acol);
            cp16(sb + r * (MSTRIDE * 2) + acol * 2,
                 B + (size_t)(bn + r) * ldB + bcb + acol);
        }
        asm volatile("cp.async.commit_group;" ::: "memory");
    };

    issue(0);
    for (int s = 0; s < S; s++) {
        if (s + 1 < S) {
            issue(s + 1);
            asm volatile("cp.async.wait_group 1;" ::: "memory");
        } else {
            asm volatile("cp.async.wait_group 0;" ::: "memory");
        }
        __syncthreads();
        uint32_t sa = smb + (s & 1) * STG;
        uint32_t sb = smb + 2 * STG + (s & 1) * STG;
        #pragma unroll
        for (int kk = 0; kk < 4; kk++) {
            uint32_t a[2][4], bfr[4][4];
            #pragma unroll
            for (int f = 0; f < 2; f++) {
                int row = wm + f * 16 + (lane & 15);
                uint32_t addr = sa + row * (MSTRIDE * 2) +
                                kk * 32 + ((lane >> 4) << 4);
                ldm4(addr, a[f][0], a[f][1], a[f][2], a[f][3]);
            }
            #pragma unroll
            for (int g = 0; g < 4; g++) {
                int row = wn + g * 16 + (lane & 7) + (((lane >> 4) & 1) << 3);
                uint32_t addr = sb + row * (MSTRIDE * 2) +
                                kk * 32 + (((lane >> 3) & 1) << 4);
                ldm4(addr, bfr[g][0], bfr[g][1], bfr[g][2], bfr[g][3]);
            }
            #pragma unroll
            for (int f = 0; f < 2; f++)
                #pragma unroll
                for (int nf = 0; nf < 8; nf++)
                    mma16816(acc[f][nf], a[f],
                             bfr[nf >> 1][(nf & 1) * 2],
                             bfr[nf >> 1][(nf & 1) * 2 + 1]);
        }
        __syncthreads();
    }

    // ---- epilogue ----
    #pragma unroll
    for (int f = 0; f < 2; f++) {
        int r0 = bm + wm + f * 16 + (lane >> 2);
        #pragma unroll
        for (int nf = 0; nf < 8; nf++) {
            int c = bn + wn + nf * 8 + (lane & 3) * 2;
            float* d = acc[f][nf];
            #pragma unroll
            for (int half = 0; half < 2; half++) {
                int r = r0 + half * 8;
                float v0 = d[half * 2 + 0];
                float v1 = d[half * 2 + 1];
                if (EPI == 0) {
                    *(float2*)&Cf[(size_t)r * ldc + c] = make_float2(v0, v1);
                } else if (EPI == 1) {
                    v0 += bias[c]     + res[(size_t)r * ldres + c];
                    v1 += bias[c + 1] + res[(size_t)r * ldres + c + 1];
                    *(float2*)&Cf[(size_t)r * ldc + c] = make_float2(v0, v1);
                } else {
                    v0 += bias[c];
                    v1 += bias[c + 1];
                    v0 = 0.5f * v0 * (1.0f + erff(v0 * 0.70710678118654752f));
                    v1 = 0.5f * v1 * (1.0f + erff(v1 * 0.70710678118654752f));
                    __nv_bfloat16 h0, l0, h1, l1;
                    bf16split(v0, h0, l0);
                    bf16split(v1, h1, l1);
                    *(__nv_bfloat162*)&Cb[(size_t)r * ldc + c] =
                        __halves2bfloat162(h0, h1);
                    *(__nv_bfloat162*)&Cb[(size_t)r * ldc + khalf + c] =
                        __halves2bfloat162(l0, l1);
                }
            }
        }
    }
}

// ------------------------- fused causal flash attention --------------------
#define FA_SMEM (4 * 64 * 68 * 4)
__global__ void __launch_bounds__(256) flash_kernel(const float* __restrict__ qkv,
                                                    __nv_bfloat16* __restrict__ oA) {
    extern __shared__ float sm[];
    float* Qt = sm;
    float* Kt = sm + 64 * 68;
    float* Vs = sm + 2 * 64 * 68;
    float* Ps = sm + 3 * 64 * 68;

    int ti = blockIdx.x;
    int bh = blockIdx.y;
    int b = bh >> 4, h = bh & 15;
    int t0 = ti * 64;
    int tid = threadIdx.x;
    int tx = tid & 15, ty = tid >> 4;
    int i0 = ty * 4, j0 = tx * 4;

    const float* Qb = qkv + ((size_t)(b * TT + t0)) * (3 * TD) + h * THD;
    const float* Kb = qkv + ((size_t)b * TT) * (3 * TD) + TD + h * THD;
    const float* Vb = qkv + ((size_t)b * TT) * (3 * TD) + 2 * TD + h * THD;

    #pragma unroll
    for (int l = 0; l < 4; l++) {
        int lin = tid + l * 256;
        int r = lin & 63, k4 = (lin >> 6) << 2;
        float4 q = *(const float4*)(Qb + (size_t)r * (3 * TD) + k4);
        Qt[(k4 + 0) * 68 + r] = q.x;
        Qt[(k4 + 1) * 68 + r] = q.y;
        Qt[(k4 + 2) * 68 + r] = q.z;
        Qt[(k4 + 3) * 68 + r] = q.w;
    }

    float m_prev[4], l_run[4], acc[4][4];
    #pragma unroll
    for (int i = 0; i < 4; i++) {
        m_prev[i] = -1e30f; l_run[i] = 0.0f;
        #pragma unroll
        for (int j = 0; j < 4; j++) acc[i][j] = 0.0f;
    }

    for (int sj = 0; sj <= ti; sj++) {
        int s0 = sj * 64;
        __syncthreads();
        #pragma unroll
        for (int l = 0; l < 4; l++) {
            int lin = tid + l * 256;
            int r = lin & 63, k4 = (lin >> 6) << 2;
            float4 kv = *(const float4*)(Kb + (size_t)(s0 + r) * (3 * TD) + k4);
            Kt[(k4 + 0) * 68 + r] = kv.x;
            Kt[(k4 + 1) * 68 + r] = kv.y;
            Kt[(k4 + 2) * 68 + r] = kv.z;
            Kt[(k4 + 3) * 68 + r] = kv.w;
            int rv = lin >> 4, c4 = (lin & 15) << 2;
            *(float4*)&Vs[rv * 68 + c4] =
                *(const float4*)(Vb + (size_t)(s0 + rv) * (3 * TD) + c4);
        }
        __syncthreads();

        float s[4][4] = {};
        #pragma unroll 4
        for (int k = 0; k < 64; k++) {
            float4 qa = *(float4*)&Qt[k * 68 + i0];
            float4 kb = *(float4*)&Kt[k * 68 + j0];
            float af[4] = {qa.x, qa.y, qa.z, qa.w};
            float bf[4] = {kb.x, kb.y, kb.z, kb.w};
            #pragma unroll
            for (int i = 0; i < 4; i++)
                #pragma unroll
                for (int j = 0; j < 4; j++) s[i][j] = fmaf(af[i], bf[j], s[i][j]);
        }
        bool diag = (sj == ti);
        #pragma unroll
        for (int i = 0; i < 4; i++)
            #pragma unroll
            for (int j = 0; j < 4; j++) {
                float v = s[i][j] * 0.125f;
                if (diag && (s0 + j0 + j) > (t0 + i0 + i)) v = -1e30f;
                s[i][j] = v;
            }

        #pragma unroll
        for (int i = 0; i < 4; i++) {
            float rmax = fmaxf(fmaxf(s[i][0], s[i][1]), fmaxf(s[i][2], s[i][3]));
            #pragma unroll
            for (int off = 8; off; off >>= 1)
                rmax = fmaxf(rmax, __shfl_xor_sync(0xffffffffu, rmax, off));
            float m_new = fmaxf(m_prev[i], rmax);
            float scale = __expf(m_prev[i] - m_new);
            float rsum = 0.0f;
            #pragma unroll
            for (int j = 0; j < 4; j++) {
                float p = __expf(s[i][j] - m_new);
                s[i][j] = p;
                rsum += p;
            }
            #pragma unroll
            for (int off = 8; off; off >>= 1)
                rsum += __shfl_xor_sync(0xffffffffu, rsum, off);
            l_run[i] = l_run[i] * scale + rsum;
            m_prev[i] = m_new;
            #pragma unroll
            for (int j = 0; j < 4; j++) acc[i][j] *= scale;
        }

        #pragma unroll
        for (int i = 0; i < 4; i++)
            #pragma unroll
            for (int j = 0; j < 4; j++) Ps[(i0 + i) * 68 + j0 + j] = s[i][j];
        __syncthreads();
        #pragma unroll 4
        for (int ss = 0; ss < 64; ss++) {
            float4 vv = *(float4*)&Vs[ss * 68 + j0];
            float pv[4];
            #pragma unroll
            for (int i = 0; i < 4; i++) pv[i] = Ps[(i0 + i) * 68 + ss];
            float vf[4] = {vv.x, vv.y, vv.z, vv.w};
            #pragma unroll
            for (int i = 0; i < 4; i++)
                #pragma unroll
                for (int j = 0; j < 4; j++) acc[i][j] = fmaf(pv[i], vf[j], acc[i][j]);
        }
    }

    #pragma unroll
    for (int i = 0; i < 4; i++) {
        float inv = 1.0f / l_run[i];
        __nv_bfloat16* base =
            oA + (size_t)(b * TT + t0 + i0 + i) * (2 * TD) + h * THD + j0;
        #pragma unroll
        for (int j = 0; j < 4; j += 2) {
            __nv_bfloat16 h0, l0, h1, l1;
            bf16split(acc[i][j + 0] * inv, h0, l0);
            bf16split(acc[i][j + 1] * inv, h1, l1);
            *(__nv_bfloat162*)(base + j) = __halves2bfloat162(h0, h1);
            *(__nv_bfloat162*)(base + TD + j) = __halves2bfloat162(l0, l1);
        }
    }
}

// ------------------------- launch ------------------------------------------
extern "C" void kernel_launch(void* const* d_in, const int* in_sizes, int n_in,
                              void* d_out, int out_size) {
    const float* x   = (const float*)d_in[0];
    const float* Wq  = (const float*)d_in[1];
    const float* Wk  = (const float*)d_in[2];
    const float* Wv  = (const float*)d_in[3];
    const float* Wo  = (const float*)d_in[4];
    const float* bo  = (const float*)d_in[5];
    const float* W1  = (const float*)d_in[6];
    const float* b1  = (const float*)d_in[7];
    const float* W2  = (const float*)d_in[8];
    const float* b2  = (const float*)d_in[9];
    const float* g1  = (const float*)d_in[10];
    const float* be1 = (const float*)d_in[11];
    const float* g2  = (const float*)d_in[12];
    const float* be2 = (const float*)d_in[13];
    float* out = (float*)d_out;

    __nv_bfloat16 *hA, *oA, *ffA, *wqkv, *wo, *w1, *w2;
    float *qkv, *x2;
    cudaGetSymbolAddress((void**)&hA,   g_hA);
    cudaGetSymbolAddress((void**)&qkv,  g_qkv);
    cudaGetSymbolAddress((void**)&oA,   g_oA);
    cudaGetSymbolAddress((void**)&x2,   g_x2);
    cudaGetSymbolAddress((void**)&ffA,  g_ffA);
    cudaGetSymbolAddress((void**)&wqkv, g_wqkv);
    cudaGetSymbolAddress((void**)&wo,   g_wo);
    cudaGetSymbolAddress((void**)&w1,   g_w1);
    cudaGetSymbolAddress((void**)&w2,   g_w2);

    static int attr_set = 0;
    if (!attr_set) {
        cudaFuncSetAttribute(flash_kernel,
                             cudaFuncAttributeMaxDynamicSharedMemorySize, FA_SMEM);
        cudaFuncSetAttribute(mgemm_kernel<0>,
                             cudaFuncAttributeMaxDynamicSharedMemorySize, MDYN);
        cudaFuncSetAttribute(mgemm_kernel<1>,
                             cudaFuncAttributeMaxDynamicSharedMemorySize, MDYN);
        cudaFuncSetAttribute(mgemm_kernel<2>,
                             cudaFuncAttributeMaxDynamicSharedMemorySize, MDYN);
        attr_set = 1;
    }

    dim3 cb(32, 8);
    // weight converts (every replay)
    qkvconv_kernel<<<dim3(2, 32, 48), cb>>>(Wq, Wk, Wv, wqkv);
    wconv_kernel<<<dim3(32, 32), cb>>>(Wo, TD, wo, 2 * TD, TD);
    wconv_kernel<<<dim3(128, 32), cb>>>(W1, TDFF, w1, 2 * TD, TD);
    wconv_kernel<<<dim3(32, 128), cb>>>(W2, TD, w2, 2 * TDFF, TDFF);

    // LN1 -> split operand
    ln_kernel<<<BT, 256>>>(x, g1, be1, hA);
    // QKV: [4096,1024] @ [1024,3072]
    mgemm_kernel<0><<<dim3(24, 32), 256, MDYN>>>(
        hA, wqkv, qkv, nullptr, TD, 2 * TD, 2 * TD, 3 * TD, 0,
        nullptr, nullptr, 0);
    // fused causal attention -> split operand
    flash_kernel<<<dim3(32, TB * TH), 256, FA_SMEM>>>(qkv, oA);
    // x2 = x + o @ Wo + bo
    mgemm_kernel<1><<<dim3(8, 32), 256, MDYN>>>(
        oA, wo, x2, nullptr, TD, 2 * TD, 2 * TD, TD, 0, bo, x, TD);
    // LN2 -> split operand
    ln_kernel<<<BT, 256>>>(x2, g2, be2, hA);
    // ff = gelu(h2 @ W1 + b1) -> split operand directly
    mgemm_kernel<2><<<dim3(32, 32), 256, MDYN>>>(
        hA, w1, nullptr, ffA, TD, 2 * TD, 2 * TD, 2 * TDFF, TDFF,
        b1, nullptr, 0);
    // out = x2 + ff @ W2 + b2
    mgemm_kernel<1><<<dim3(8, 32), 256, MDYN>>>(
        ffA, w2, out, nullptr, TDFF, 2 * TDFF, 2 * TDFF, TD, 0, b2, x2, TD);
}

// round 9
// speedup vs baseline: 2.7766x; 1.3886x over previous
#include <cuda_runtime.h>
#include <cuda_bf16.h>
#include <math.h>
#include <stdint.h>

// Problem dims
#define TB   2
#define TT   2048
#define TD   1024
#define TH   16
#define THD  64
#define TDFF 4096
#define BT   (TB*TT)

// ------------------------- scratch (device globals) ------------------------
__device__ __nv_bfloat16 g_hA  [(size_t)BT * 2 * TD];     // LN out, split
__device__ __nv_bfloat16 g_qkvb[(size_t)BT * 6 * TD];     // qkv split: hi 3TD | lo 3TD
__device__ __nv_bfloat16 g_oA  [(size_t)BT * 2 * TD];     // attn out, split
__device__ float         g_x2  [(size_t)BT * TD];
__device__ __nv_bfloat16 g_ffA [(size_t)BT * 2 * TDFF];
// B-operands (weights), K-major [N][2K]: (hi | lo)
__device__ __nv_bfloat16 g_wqkv[(size_t)(3*TD) * (2*TD)];
__device__ __nv_bfloat16 g_wo  [(size_t)TD * (2*TD)];
__device__ __nv_bfloat16 g_w1  [(size_t)TDFF * (2*TD)];
__device__ __nv_bfloat16 g_w2  [(size_t)TD * (2*TDFF)];

__device__ __forceinline__ uint32_t smem_u32(const void* p) {
    uint32_t a;
    asm("{ .reg .u64 t; cvta.to.shared.u64 t, %1; cvt.u32.u64 %0, t; }"
        : "=r"(a) : "l"(p));
    return a;
}
__device__ __forceinline__ void bf16split(float v, __nv_bfloat16& hi,
                                          __nv_bfloat16& lo) {
    hi = __float2bfloat16(v);
    lo = __float2bfloat16(v - __bfloat162float(hi));
}
__device__ __forceinline__ uint32_t packbf2(float x, float y) {
    __nv_bfloat162 t = __floats2bfloat162_rn(x, y);
    return *(uint32_t*)&t;
}
__device__ __forceinline__ void cp16(uint32_t sdst, const void* gsrc) {
    asm volatile("cp.async.cg.shared.global [%0], [%1], 16;"
                 :: "r"(sdst), "l"(gsrc));
}
__device__ __forceinline__ void ldm4(uint32_t addr, uint32_t& r0, uint32_t& r1,
                                     uint32_t& r2, uint32_t& r3) {
    asm volatile("ldmatrix.sync.aligned.m8n8.x4.shared.b16 {%0,%1,%2,%3}, [%4];"
                 : "=r"(r0), "=r"(r1), "=r"(r2), "=r"(r3) : "r"(addr));
}
__device__ __forceinline__ void ldm4t(uint32_t addr, uint32_t& r0, uint32_t& r1,
                                      uint32_t& r2, uint32_t& r3) {
    asm volatile("ldmatrix.sync.aligned.m8n8.x4.trans.shared.b16 {%0,%1,%2,%3}, [%4];"
                 : "=r"(r0), "=r"(r1), "=r"(r2), "=r"(r3) : "r"(addr));
}
__device__ __forceinline__ void mma16816(float* d, const uint32_t* a,
                                         uint32_t b0, uint32_t b1) {
    asm volatile(
        "mma.sync.aligned.m16n8k16.row.col.f32.bf16.bf16.f32 "
        "{%0,%1,%2,%3}, {%4,%5,%6,%7}, {%8,%9}, {%0,%1,%2,%3};"
        : "+f"(d[0]), "+f"(d[1]), "+f"(d[2]), "+f"(d[3])
        : "r"(a[0]), "r"(a[1]), "r"(a[2]), "r"(a[3]), "r"(b0), "r"(b1));
}

// ------------------------- weight convert (tiled transpose + split) --------
__global__ void __launch_bounds__(256) wconv_kernel(
    const float* __restrict__ src, int srcld,
    __nv_bfloat16* __restrict__ dst, int dstld, int khalf) {
    __shared__ float t[32][33];
    int k0 = blockIdx.y * 32, n0 = blockIdx.x * 32;
    int tx = threadIdx.x, ty = threadIdx.y;
    #pragma unroll
    for (int i = 0; i < 4; i++)
        t[ty + 8 * i][tx] = src[(size_t)(k0 + ty + 8 * i) * srcld + n0 + tx];
    __syncthreads();
    #pragma unroll
    for (int i = 0; i < 4; i++) {
        int n = n0 + ty + 8 * i, k = k0 + tx;
        __nv_bfloat16 hi, lo;
        bf16split(t[tx][ty + 8 * i], hi, lo);
        dst[(size_t)n * dstld + k] = hi;
        dst[(size_t)n * dstld + khalf + k] = lo;
    }
}

__global__ void __launch_bounds__(256) qkvconv_kernel(
    const float* __restrict__ Wq, const float* __restrict__ Wk,
    const float* __restrict__ Wv, __nv_bfloat16* __restrict__ dst) {
    __shared__ float t[32][33];
    int z = blockIdx.z;
    int third = z >> 4, h = z & 15;
    const float* W = (third == 0) ? Wq : ((third == 1) ? Wk : Wv);
    const float* src = W + (size_t)h * TD * THD;
    int k0 = blockIdx.y * 32, n0 = blockIdx.x * 32;
    int tx = threadIdx.x, ty = threadIdx.y;
    #pragma unroll
    for (int i = 0; i < 4; i++)
        t[ty + 8 * i][tx] = src[(size_t)(k0 + ty + 8 * i) * THD + n0 + tx];
    __syncthreads();
    #pragma unroll
    for (int i = 0; i < 4; i++) {
        int nl = n0 + ty + 8 * i, k = k0 + tx;
        int n = third * TD + h * THD + nl;
        __nv_bfloat16 hi, lo;
        bf16split(t[tx][ty + 8 * i], hi, lo);
        dst[(size_t)n * (2 * TD) + k] = hi;
        dst[(size_t)n * (2 * TD) + TD + k] = lo;
    }
}

// ------------------------- LayerNorm -> split bf16 A operand ---------------
__global__ void __launch_bounds__(256) ln_kernel(const float* __restrict__ x,
                                                 const float* __restrict__ g,
                                                 const float* __restrict__ b,
                                                 __nv_bfloat16* __restrict__ outA) {
    __shared__ float sh[16];
    int row = blockIdx.x;
    int tid = threadIdx.x;
    const float* xr = x + (size_t)row * TD;
    float4 v = *(const float4*)(xr + tid * 4);
    float s  = v.x + v.y + v.z + v.w;
    float sq = v.x * v.x + v.y * v.y + v.z * v.z + v.w * v.w;
    #pragma unroll
    for (int o = 16; o; o >>= 1) {
        s  += __shfl_xor_sync(0xffffffffu, s, o);
        sq += __shfl_xor_sync(0xffffffffu, sq, o);
    }
    if ((tid & 31) == 0) { sh[tid >> 5] = s; sh[(tid >> 5) + 8] = sq; }
    __syncthreads();
    if (tid < 32) {
        float a = (tid < 8) ? sh[tid] : 0.0f;
        float c = (tid < 8) ? sh[tid + 8] : 0.0f;
        #pragma unroll
        for (int o = 4; o; o >>= 1) {
            a += __shfl_xor_sync(0xffffffffu, a, o);
            c += __shfl_xor_sync(0xffffffffu, c, o);
        }
        if (tid == 0) { sh[0] = a; sh[1] = c; }
    }
    __syncthreads();
    float mu  = sh[0] * (1.0f / TD);
    float var = sh[1] * (1.0f / TD) - mu * mu;
    float rs  = rsqrtf(var + 1e-5f);
    float4 gg = *(const float4*)(g + tid * 4);
    float4 bb = *(const float4*)(b + tid * 4);
    float o0 = (v.x - mu) * rs * gg.x + bb.x;
    float o1 = (v.y - mu) * rs * gg.y + bb.y;
    float o2 = (v.z - mu) * rs * gg.z + bb.z;
    float o3 = (v.w - mu) * rs * gg.w + bb.w;
    __nv_bfloat16 h0, l0, h1, l1, h2, l2, h3, l3;
    bf16split(o0, h0, l0); bf16split(o1, h1, l1);
    bf16split(o2, h2, l2); bf16split(o3, h3, l3);
    __nv_bfloat16* base = outA + (size_t)row * (2 * TD) + tid * 4;
    *(__nv_bfloat162*)(base + 0) = __halves2bfloat162(h0, h1);
    *(__nv_bfloat162*)(base + 2) = __halves2bfloat162(h2, h3);
    *(__nv_bfloat162*)(base + TD + 0) = __halves2bfloat162(l0, l1);
    *(__nv_bfloat162*)(base + TD + 2) = __halves2bfloat162(l2, l3);
}

// ------------------------- HMMA split-bf16 GEMM ----------------------------
// EPI: 0 fp32; 1 +bias+res fp32; 2 +bias GELU split-bf16; 3 plain split-bf16
#define MSTRIDE 72
#define STG     (128 * MSTRIDE * 2)
#define MDYN    (4 * STG)

template <int EPI>
__global__ void __launch_bounds__(256) mgemm_kernel(
    const __nv_bfloat16* __restrict__ A, const __nv_bfloat16* __restrict__ B,
    float* __restrict__ Cf, __nv_bfloat16* __restrict__ Cb,
    int K, int ldA, int ldB, int ldc, int khalf,
    const float* __restrict__ bias, const float* __restrict__ res, int ldres) {
    extern __shared__ char smp[];
    uint32_t smb = smem_u32(smp);
    int tid = threadIdx.x, wid = tid >> 5, lane = tid & 31;
    int bm = blockIdx.y * 128, bn = blockIdx.x * 128;
    int wm = (wid & 3) * 32, wn = (wid >> 2) * 64;
    const int S = (3 * K) >> 6;

    int arow = tid >> 3, acol = (tid & 7) * 8;

    float acc[2][8][4];
    #pragma unroll
    for (int i = 0; i < 2; i++)
        #pragma unroll
        for (int j = 0; j < 8; j++)
            #pragma unroll
            for (int q = 0; q < 4; q++) acc[i][j][q] = 0.0f;

    auto issue = [&](int s) {
        int k0 = s << 6;
        int blk = k0 / K, cin = k0 - blk * K;
        int acb = ((blk == 1) ? K : 0) + cin;
        int bcb = ((blk == 2) ? K : 0) + cin;
        uint32_t sa = smb + (s & 1) * STG;
        uint32_t sb = smb + 2 * STG + (s & 1) * STG;
        #pragma unroll
        for (int p = 0; p < 4; p++) {
            int r = p * 32 + arow;
            cp16(sa + r * (MSTRIDE * 2) + acol * 2,
                 A + (size_t)(bm + r) * ldA + acb + acol);
            cp16(sb + r * (MSTRIDE * 2) + acol * 2,
                 B + (size_t)(bn + r) * ldB + bcb + acol);
        }
        asm volatile("cp.async.commit_group;" ::: "memory");
    };

    issue(0);
    for (int s = 0; s < S; s++) {
        if (s + 1 < S) {
            issue(s + 1);
            asm volatile("cp.async.wait_group 1;" ::: "memory");
        } else {
            asm volatile("cp.async.wait_group 0;" ::: "memory");
        }
        __syncthreads();
        uint32_t sa = smb + (s & 1) * STG;
        uint32_t sb = smb + 2 * STG + (s & 1) * STG;
        #pragma unroll
        for (int kk = 0; kk < 4; kk++) {
            uint32_t a[2][4], bfr[4][4];
            #pragma unroll
            for (int f = 0; f < 2; f++) {
                int row = wm + f * 16 + (lane & 15);
                uint32_t addr = sa + row * (MSTRIDE * 2) +
                                kk * 32 + ((lane >> 4) << 4);
                ldm4(addr, a[f][0], a[f][1], a[f][2], a[f][3]);
            }
            #pragma unroll
            for (int g = 0; g < 4; g++) {
                int row = wn + g * 16 + (lane & 7) + (((lane >> 4) & 1) << 3);
                uint32_t addr = sb + row * (MSTRIDE * 2) +
                                kk * 32 + (((lane >> 3) & 1) << 4);
                ldm4(addr, bfr[g][0], bfr[g][1], bfr[g][2], bfr[g][3]);
            }
            #pragma unroll
            for (int f = 0; f < 2; f++)
                #pragma unroll
                for (int nf = 0; nf < 8; nf++)
                    mma16816(acc[f][nf], a[f],
                             bfr[nf >> 1][(nf & 1) * 2],
                             bfr[nf >> 1][(nf & 1) * 2 + 1]);
        }
        __syncthreads();
    }

    #pragma unroll
    for (int f = 0; f < 2; f++) {
        int r0 = bm + wm + f * 16 + (lane >> 2);
        #pragma unroll
        for (int nf = 0; nf < 8; nf++) {
            int c = bn + wn + nf * 8 + (lane & 3) * 2;
            float* d = acc[f][nf];
            #pragma unroll
            for (int half = 0; half < 2; half++) {
                int r = r0 + half * 8;
                float v0 = d[half * 2 + 0];
                float v1 = d[half * 2 + 1];
                if (EPI == 0) {
                    *(float2*)&Cf[(size_t)r * ldc + c] = make_float2(v0, v1);
                } else if (EPI == 1) {
                    v0 += bias[c]     + res[(size_t)r * ldres + c];
                    v1 += bias[c + 1] + res[(size_t)r * ldres + c + 1];
                    *(float2*)&Cf[(size_t)r * ldc + c] = make_float2(v0, v1);
                } else {
                    if (EPI == 2) {
                        v0 += bias[c];
                        v1 += bias[c + 1];
                        v0 = 0.5f * v0 * (1.0f + erff(v0 * 0.70710678118654752f));
                        v1 = 0.5f * v1 * (1.0f + erff(v1 * 0.70710678118654752f));
                    }
                    __nv_bfloat16 h0, l0, h1, l1;
                    bf16split(v0, h0, l0);
                    bf16split(v1, h1, l1);
                    *(__nv_bfloat162*)&Cb[(size_t)r * ldc + c] =
                        __halves2bfloat162(h0, h1);
                    *(__nv_bfloat162*)&Cb[(size_t)r * ldc + khalf + c] =
                        __halves2bfloat162(l0, l1);
                }
            }
        }
    }
}

// ------------------------- HMMA flash attention ----------------------------
// 128 threads / 4 warps; warp w owns query rows w*16..w*16+15 of a 64-row tile.
// Split bf16 3-term for QK^T and PV; P repacked in registers.
#define FROW 72
#define FMAT (64 * FROW)                 // bf16 elements per smem matrix
#define FB_SMEM (6 * FMAT * 2)           // Qh Ql Kh Kl Vh Vl = 55296 B
__global__ void __launch_bounds__(128) flashT_kernel(
    const __nv_bfloat16* __restrict__ qkvb, __nv_bfloat16* __restrict__ oA) {
    extern __shared__ __nv_bfloat16 fsm[];
    __nv_bfloat16* Qh = fsm;
    __nv_bfloat16* Ql = fsm + FMAT;
    __nv_bfloat16* Kh = fsm + 2 * FMAT;
    __nv_bfloat16* Kl = fsm + 3 * FMAT;
    __nv_bfloat16* Vh = fsm + 4 * FMAT;
    __nv_bfloat16* Vl = fsm + 5 * FMAT;
    uint32_t sKh = smem_u32(Kh), sKl = smem_u32(Kl);
    uint32_t sVh = smem_u32(Vh), sVl = smem_u32(Vl);

    int ti = blockIdx.x, bh = blockIdx.y;
    int b = bh >> 4, h = bh & 15;
    int t0 = ti * 64;
    int tid = threadIdx.x, wid = tid >> 5, lane = tid & 31;
    const int ld = 6 * TD;

    const __nv_bfloat16* rowbase = qkvb + (size_t)(b * TT) * ld;
    const __nv_bfloat16* Qhg = rowbase + (size_t)t0 * ld + h * THD;
    const __nv_bfloat16* Khg = rowbase + TD + h * THD;
    const __nv_bfloat16* Vhg = rowbase + 2 * TD + h * THD;

    // copy 64x64 bf16 matrix (hi and lo halves) into smem
    auto copy6464 = [&](__nv_bfloat16* dst, const __nv_bfloat16* src) {
        #pragma unroll
        for (int it = 0; it < 4; it++) {
            int u = it * 128 + tid;
            int r = u >> 3, q = u & 7;
            *(uint4*)&dst[r * FROW + q * 8] =
                *(const uint4*)(src + (size_t)r * ld + q * 8);
        }
    };

    // Q tiles -> smem -> register fragments (once)
    copy6464(Qh, Qhg);
    copy6464(Ql, Qhg + 3 * TD);
    __syncthreads();
    uint32_t qh[4][4], ql[4][4];
    {
        uint32_t sQh = smem_u32(Qh), sQl = smem_u32(Ql);
        int row = wid * 16 + (lane & 15);
        #pragma unroll
        for (int kk = 0; kk < 4; kk++) {
            uint32_t off = row * (FROW * 2) + kk * 32 + ((lane >> 4) << 4);
            ldm4(sQh + off, qh[kk][0], qh[kk][1], qh[kk][2], qh[kk][3]);
            ldm4(sQl + off, ql[kk][0], ql[kk][1], ql[kk][2], ql[kk][3]);
        }
    }

    float oacc[8][4];
    #pragma unroll
    for (int nf = 0; nf < 8; nf++)
        #pragma unroll
        for (int q = 0; q < 4; q++) oacc[nf][q] = 0.0f;
    float m0 = -1e30f, m1 = -1e30f, l0 = 0.0f, l1 = 0.0f;

    for (int sj = 0; sj <= ti; sj++) {
        int s0 = sj * 64;
        __syncthreads();
        copy6464(Kh, Khg + (size_t)s0 * ld);
        copy6464(Kl, Khg + (size_t)s0 * ld + 3 * TD);
        copy6464(Vh, Vhg + (size_t)s0 * ld);
        copy6464(Vl, Vhg + (size_t)s0 * ld + 3 * TD);
        __syncthreads();

        // ---- S = Q K^T (3 split terms) ----
        float sacc[8][4];
        #pragma unroll
        for (int nf = 0; nf < 8; nf++)
            #pragma unroll
            for (int q = 0; q < 4; q++) sacc[nf][q] = 0.0f;
        #pragma unroll
        for (int kk = 0; kk < 4; kk++) {
            uint32_t bh4[4][4], bl4[4][4];
            int row = (lane & 7) + (((lane >> 4) & 1) << 3);
            uint32_t coff = kk * 32 + (((lane >> 3) & 1) << 4);
            #pragma unroll
            for (int g = 0; g < 4; g++) {
                uint32_t off = (g * 16 + row) * (FROW * 2) + coff;
                ldm4(sKh + off, bh4[g][0], bh4[g][1], bh4[g][2], bh4[g][3]);
                ldm4(sKl + off, bl4[g][0], bl4[g][1], bl4[g][2], bl4[g][3]);
            }
            #pragma unroll
            for (int nf = 0; nf < 8; nf++) {
                uint32_t b0 = bh4[nf >> 1][(nf & 1) * 2];
                uint32_t b1 = bh4[nf >> 1][(nf & 1) * 2 + 1];
                mma16816(sacc[nf], qh[kk], b0, b1);
                mma16816(sacc[nf], ql[kk], b0, b1);
                mma16816(sacc[nf], qh[kk],
                         bl4[nf >> 1][(nf & 1) * 2],
                         bl4[nf >> 1][(nf & 1) * 2 + 1]);
            }
        }

        // ---- scale + causal mask ----
        bool diag = (sj == ti);
        int rloc0 = wid * 16 + (lane >> 2);
        #pragma unroll
        for (int nf = 0; nf < 8; nf++) {
            #pragma unroll
            for (int q = 0; q < 4; q++) {
                float v = sacc[nf][q] * 0.125f;
                if (diag) {
                    int col = nf * 8 + (lane & 3) * 2 + (q & 1);
                    int rr = rloc0 + (q >> 1) * 8;
                    if (col > rr) v = -1e30f;
                }
                sacc[nf][q] = v;
            }
        }

        // ---- online softmax (quad-lane reduction; rows rloc0, rloc0+8) ----
        float mx0 = -1e30f, mx1 = -1e30f;
        #pragma unroll
        for (int nf = 0; nf < 8; nf++) {
            mx0 = fmaxf(mx0, fmaxf(sacc[nf][0], sacc[nf][1]));
            mx1 = fmaxf(mx1, fmaxf(sacc[nf][2], sacc[nf][3]));
        }
        #pragma unroll
        for (int o = 1; o <= 2; o <<= 1) {
            mx0 = fmaxf(mx0, __shfl_xor_sync(0xffffffffu, mx0, o));
            mx1 = fmaxf(mx1, __shfl_xor_sync(0xffffffffu, mx1, o));
        }
        float mn0 = fmaxf(m0, mx0), mn1 = fmaxf(m1, mx1);
        float sc0 = __expf(m0 - mn0), sc1 = __expf(m1 - mn1);
        float rs0 = 0.0f, rs1 = 0.0f;
        #pragma unroll
        for (int nf = 0; nf < 8; nf++) {
            sacc[nf][0] = __expf(sacc[nf][0] - mn0);
            sacc[nf][1] = __expf(sacc[nf][1] - mn0);
            sacc[nf][2] = __expf(sacc[nf][2] - mn1);
            sacc[nf][3] = __expf(sacc[nf][3] - mn1);
            rs0 += sacc[nf][0] + sacc[nf][1];
            rs1 += sacc[nf][2] + sacc[nf][3];
        }
        #pragma unroll
        for (int o = 1; o <= 2; o <<= 1) {
            rs0 += __shfl_xor_sync(0xffffffffu, rs0, o);
            rs1 += __shfl_xor_sync(0xffffffffu, rs1, o);
        }
        l0 = l0 * sc0 + rs0; l1 = l1 * sc1 + rs1;
        m0 = mn0; m1 = mn1;
        #pragma unroll
        for (int nf = 0; nf < 8; nf++) {
            oacc[nf][0] *= sc0; oacc[nf][1] *= sc0;
            oacc[nf][2] *= sc1; oacc[nf][3] *= sc1;
        }

        // ---- O += P @ V (P repacked in registers, 3 split terms) ----
        #pragma unroll
        for (int kk = 0; kk < 4; kk++) {
            float* p0 = sacc[2 * kk];
            float* p1 = sacc[2 * kk + 1];
            uint32_t aPh[4], aPl[4];
            {
                __nv_bfloat16 hh, llv;
                float r00, r01, r10, r11;
                bf16split(p0[0], hh, llv); r00 = __bfloat162float(llv);
                bf16split(p0[1], hh, llv); r01 = __bfloat162float(llv);
                aPh[0] = packbf2(p0[0], p0[1]); aPl[0] = packbf2(r00, r01);
                bf16split(p0[2], hh, llv); r10 = __bfloat162float(llv);
                bf16split(p0[3], hh, llv); r11 = __bfloat162float(llv);
                aPh[1] = packbf2(p0[2], p0[3]); aPl[1] = packbf2(r10, r11);
                bf16split(p1[0], hh, llv); r00 = __bfloat162float(llv);
                bf16split(p1[1], hh, llv); r01 = __bfloat162float(llv);
                aPh[2] = packbf2(p1[0], p1[1]); aPl[2] = packbf2(r00, r01);
                bf16split(p1[2], hh, llv); r10 = __bfloat162float(llv);
                bf16split(p1[3], hh, llv); r11 = __bfloat162float(llv);
                aPh[3] = packbf2(p1[2], p1[3]); aPl[3] = packbf2(r10, r11);
            }
            uint32_t vh4[4][4], vl4[4][4];
            int srow = kk * 16 + (lane & 15);
            #pragma unroll
            for (int g = 0; g < 4; g++) {
                uint32_t off = srow * (FROW * 2) +
                               (g * 16 + ((lane >> 4) << 3)) * 2;
                ldm4t(sVh + off, vh4[g][0], vh4[g][1], vh4[g][2], vh4[g][3]);
                ldm4t(sVl + off, vl4[g][0], vl4[g][1], vl4[g][2], vl4[g][3]);
            }
            #pragma unroll
            for (int nf = 0; nf < 8; nf++) {
                uint32_t b0 = vh4[nf >> 1][(nf & 1) * 2];
                uint32_t b1 = vh4[nf >> 1][(nf & 1) * 2 + 1];
                mma16816(oacc[nf], aPh, b0, b1);
                mma16816(oacc[nf], aPl, b0, b1);
                mma16816(oacc[nf], aPh,
                         vl4[nf >> 1][(nf & 1) * 2],
                         vl4[nf >> 1][(nf & 1) * 2 + 1]);
            }
        }
    }

    // ---- finalize + split-bf16 store ----
    float inv0 = 1.0f / l0, inv1 = 1.0f / l1;
    int r0 = t0 + wid * 16 + (lane >> 2);
    #pragma unroll
    for (int nf = 0; nf < 8; nf++) {
        int d = nf * 8 + (lane & 3) * 2;
        __nv_bfloat16* base0 =
            oA + (size_t)(b * TT + r0) * (2 * TD) + h * THD + d;
        __nv_bfloat16* base1 =
            oA + (size_t)(b * TT + r0 + 8) * (2 * TD) + h * THD + d;
        __nv_bfloat16 h0, lo0, h1, lo1;
        bf16split(oacc[nf][0] * inv0, h0, lo0);
        bf16split(oacc[nf][1] * inv0, h1, lo1);
        *(__nv_bfloat162*)base0 = __halves2bfloat162(h0, h1);
        *(__nv_bfloat162*)(base0 + TD) = __halves2bfloat162(lo0, lo1);
        bf16split(oacc[nf][2] * inv1, h0, lo0);
        bf16split(oacc[nf][3] * inv1, h1, lo1);
        *(__nv_bfloat162*)base1 = __halves2bfloat162(h0, h1);
        *(__nv_bfloat162*)(base1 + TD) = __halves2bfloat162(lo0, lo1);
    }
}

// ------------------------- launch ------------------------------------------
extern "C" void kernel_launch(void* const* d_in, const int* in_sizes, int n_in,
                              void* d_out, int out_size) {
    const float* x   = (const float*)d_in[0];
    const float* Wq  = (const float*)d_in[1];
    const float* Wk  = (const float*)d_in[2];
    const float* Wv  = (const float*)d_in[3];
    const float* Wo  = (const float*)d_in[4];
    const float* bo  = (const float*)d_in[5];
    const float* W1  = (const float*)d_in[6];
    const float* b1  = (const float*)d_in[7];
    const float* W2  = (const float*)d_in[8];
    const float* b2  = (const float*)d_in[9];
    const float* g1  = (const float*)d_in[10];
    const float* be1 = (const float*)d_in[11];
    const float* g2  = (const float*)d_in[12];
    const float* be2 = (const float*)d_in[13];
    float* out = (float*)d_out;

    __nv_bfloat16 *hA, *qkvb, *oA, *ffA, *wqkv, *wo, *w1, *w2;
    float *x2;
    cudaGetSymbolAddress((void**)&hA,   g_hA);
    cudaGetSymbolAddress((void**)&qkvb, g_qkvb);
    cudaGetSymbolAddress((void**)&oA,   g_oA);
    cudaGetSymbolAddress((void**)&x2,   g_x2);
    cudaGetSymbolAddress((void**)&ffA,  g_ffA);
    cudaGetSymbolAddress((void**)&wqkv, g_wqkv);
    cudaGetSymbolAddress((void**)&wo,   g_wo);
    cudaGetSymbolAddress((void**)&w1,   g_w1);
    cudaGetSymbolAddress((void**)&w2,   g_w2);

    static int attr_set = 0;
    if (!attr_set) {
        cudaFuncSetAttribute(flashT_kernel,
                             cudaFuncAttributeMaxDynamicSharedMemorySize, FB_SMEM);
        cudaFuncSetAttribute(mgemm_kernel<0>,
                             cudaFuncAttributeMaxDynamicSharedMemorySize, MDYN);
        cudaFuncSetAttribute(mgemm_kernel<1>,
                             cudaFuncAttributeMaxDynamicSharedMemorySize, MDYN);
        cudaFuncSetAttribute(mgemm_kernel<2>,
                             cudaFuncAttributeMaxDynamicSharedMemorySize, MDYN);
        cudaFuncSetAttribute(mgemm_kernel<3>,
                             cudaFuncAttributeMaxDynamicSharedMemorySize, MDYN);
        attr_set = 1;
    }

    dim3 cb(32, 8);
    qkvconv_kernel<<<dim3(2, 32, 48), cb>>>(Wq, Wk, Wv, wqkv);
    wconv_kernel<<<dim3(32, 32), cb>>>(Wo, TD, wo, 2 * TD, TD);
    wconv_kernel<<<dim3(128, 32), cb>>>(W1, TDFF, w1, 2 * TD, TD);
    wconv_kernel<<<dim3(32, 128), cb>>>(W2, TD, w2, 2 * TDFF, TDFF);

    // LN1 -> split operand
    ln_kernel<<<BT, 256>>>(x, g1, be1, hA);
    // QKV GEMM -> split bf16 output (attention operands)
    mgemm_kernel<3><<<dim3(24, 32), 256, MDYN>>>(
        hA, wqkv, nullptr, qkvb, TD, 2 * TD, 2 * TD, 6 * TD, 3 * TD,
        nullptr, nullptr, 0);
    // HMMA flash attention -> split operand
    flashT_kernel<<<dim3(32, TB * TH), 128, FB_SMEM>>>(qkvb, oA);
    // x2 = x + o @ Wo + bo
    mgemm_kernel<1><<<dim3(8, 32), 256, MDYN>>>(
        oA, wo, x2, nullptr, TD, 2 * TD, 2 * TD, TD, 0, bo, x, TD);
    // LN2 -> split operand
    ln_kernel<<<BT, 256>>>(x2, g2, be2, hA);
    // ff = gelu(h2 @ W1 + b1) -> split operand
    mgemm_kernel<2><<<dim3(32, 32), 256, MDYN>>>(
        hA, w1, nullptr, ffA, TD, 2 * TD, 2 * TD, 2 * TDFF, TDFF,
        b1, nullptr, 0);
    // out = x2 + ff @ W2 + b2
    mgemm_kernel<1><<<dim3(8, 32), 256, MDYN>>>(
        ffA, w2, out, nullptr, TDFF, 2 * TDFF, 2 * TDFF, TD, 0, b2, x2, TD);
}